// round 1
// baseline (speedup 1.0000x reference)
#include <cuda_runtime.h>
#include <math.h>

// Problem constants
#define BATCH 4
#define CH    512
#define HW    4096
#define NGRP  32
#define CPG   (CH / NGRP)          // 16 channels per group

static const size_t CHW = (size_t)CH * HW;        // 2 097 152
static const size_t SHW = (size_t)HW * HW;        // 16 777 216

// Scratch (static device globals — allocation-free per harness rules)
__device__ float g_xn[(size_t)BATCH * CH * HW];
__device__ float g_q [(size_t)BATCH * CH * HW];
__device__ float g_k [(size_t)BATCH * CH * HW];
__device__ float g_v [(size_t)BATCH * CH * HW];
__device__ float g_o [(size_t)BATCH * CH * HW];
__device__ float g_s [(size_t)BATCH * HW * HW];   // 256 MB score/attn matrix

// ---------------------------------------------------------------------------
// GroupNorm: one block per (batch, group). 16*4096 = 65536 elems per group.
// ---------------------------------------------------------------------------
__global__ __launch_bounds__(256) void groupnorm_kernel(
    const float* __restrict__ x,
    const float* __restrict__ scale,
    const float* __restrict__ bias,
    float* __restrict__ xn)
{
    const int b = blockIdx.x / NGRP;
    const int g = blockIdx.x % NGRP;
    const size_t base = ((size_t)b * CH + (size_t)g * CPG) * HW;
    const int n4 = CPG * HW / 4;                      // 16384 float4s

    const float4* xin = reinterpret_cast<const float4*>(x + base);
    float s = 0.f, ss = 0.f;
    for (int i = threadIdx.x; i < n4; i += 256) {
        float4 t = xin[i];
        s  += t.x + t.y + t.z + t.w;
        ss += t.x * t.x + t.y * t.y + t.z * t.z + t.w * t.w;
    }

    __shared__ float r1[256], r2[256];
    r1[threadIdx.x] = s; r2[threadIdx.x] = ss;
    __syncthreads();
    for (int off = 128; off > 0; off >>= 1) {
        if (threadIdx.x < off) {
            r1[threadIdx.x] += r1[threadIdx.x + off];
            r2[threadIdx.x] += r2[threadIdx.x + off];
        }
        __syncthreads();
    }
    const float inv_n = 1.f / (float)(CPG * HW);
    const float mean  = r1[0] * inv_n;
    const float var   = fmaxf(r2[0] * inv_n - mean * mean, 0.f);
    const float rstd  = rsqrtf(var + 1e-6f);

    float4* xo = reinterpret_cast<float4*>(xn + base);
    for (int i = threadIdx.x; i < n4; i += 256) {
        const int c   = g * CPG + (i >> 10);          // (i*4)/4096
        const float a = scale[c] * rstd;
        const float d = bias[c] - mean * a;
        float4 t = xin[i];
        t.x = t.x * a + d; t.y = t.y * a + d;
        t.z = t.z * a + d; t.w = t.w * a + d;
        xo[i] = t;
    }
}

// ---------------------------------------------------------------------------
// Tiled SGEMM: C[m,n] = alpha * sum_k A(m,k)*B(k,n) + bias[m] + addc
//   TA: A stored [k*M + m]  (K-major / "transposed")
//  !TA: A stored [m*K + k]  (row-major)
//   TB: B stored [n*K + k]
//  !TB: B stored [k*N + n]
// BM=BN=128, BK=8, 256 threads, 8x8 microtile. All dims multiples of tile.
// blockIdx.z = batch (strides sA/sB/sC; 0 for shared weights).
// ---------------------------------------------------------------------------
#define BM 128
#define BN 128
#define BK 8
#define TM 8
#define TN 8

template<bool TA, bool TB>
__global__ __launch_bounds__(256) void sgemm_kernel(
    const float* __restrict__ A,
    const float* __restrict__ B,
    const float* __restrict__ bias,
    float* __restrict__ C,
    int M, int N, int K,
    float alpha, float addc,
    size_t sA, size_t sB, size_t sC)
{
    __shared__ float As[BK][BM];
    __shared__ float Bs[BK][BN];

    A += (size_t)blockIdx.z * sA;
    B += (size_t)blockIdx.z * sB;
    C += (size_t)blockIdx.z * sC;

    const int bm  = blockIdx.y * BM;
    const int bn  = blockIdx.x * BN;
    const int tid = threadIdx.x;
    const int tx  = tid & 15;     // 0..15  -> column group
    const int ty  = tid >> 4;     // 0..15  -> row group

    float acc[TM][TN];
    #pragma unroll
    for (int i = 0; i < TM; i++)
        #pragma unroll
        for (int j = 0; j < TN; j++) acc[i][j] = 0.f;

    for (int bk = 0; bk < K; bk += BK) {
        // ---- load A tile into As[k][m] ----
        if (TA) {
            const int k = tid >> 5;              // 0..7
            const int m = (tid & 31) << 2;       // 0..124
            const float4 t = *reinterpret_cast<const float4*>(
                &A[(size_t)(bk + k) * M + bm + m]);
            As[k][m + 0] = t.x; As[k][m + 1] = t.y;
            As[k][m + 2] = t.z; As[k][m + 3] = t.w;
        } else {
            const int m = tid >> 1;              // 0..127
            const int k = (tid & 1) << 2;        // 0 or 4
            const float4 t = *reinterpret_cast<const float4*>(
                &A[(size_t)(bm + m) * K + bk + k]);
            As[k + 0][m] = t.x; As[k + 1][m] = t.y;
            As[k + 2][m] = t.z; As[k + 3][m] = t.w;
        }
        // ---- load B tile into Bs[k][n] ----
        if (!TB) {
            const int k = tid >> 5;
            const int n = (tid & 31) << 2;
            const float4 t = *reinterpret_cast<const float4*>(
                &B[(size_t)(bk + k) * N + bn + n]);
            Bs[k][n + 0] = t.x; Bs[k][n + 1] = t.y;
            Bs[k][n + 2] = t.z; Bs[k][n + 3] = t.w;
        } else {
            const int n = tid >> 1;
            const int k = (tid & 1) << 2;
            const float4 t = *reinterpret_cast<const float4*>(
                &B[(size_t)(bn + n) * K + bk + k]);
            Bs[k + 0][n] = t.x; Bs[k + 1][n] = t.y;
            Bs[k + 2][n] = t.z; Bs[k + 3][n] = t.w;
        }
        __syncthreads();

        #pragma unroll
        for (int k = 0; k < BK; k++) {
            float af[TM], bf[TN];
            const float4 a0 = *reinterpret_cast<const float4*>(&As[k][ty * TM]);
            const float4 a1 = *reinterpret_cast<const float4*>(&As[k][ty * TM + 4]);
            af[0]=a0.x; af[1]=a0.y; af[2]=a0.z; af[3]=a0.w;
            af[4]=a1.x; af[5]=a1.y; af[6]=a1.z; af[7]=a1.w;
            const float4 b0 = *reinterpret_cast<const float4*>(&Bs[k][tx * TN]);
            const float4 b1 = *reinterpret_cast<const float4*>(&Bs[k][tx * TN + 4]);
            bf[0]=b0.x; bf[1]=b0.y; bf[2]=b0.z; bf[3]=b0.w;
            bf[4]=b1.x; bf[5]=b1.y; bf[6]=b1.z; bf[7]=b1.w;
            #pragma unroll
            for (int i = 0; i < TM; i++)
                #pragma unroll
                for (int j = 0; j < TN; j++)
                    acc[i][j] += af[i] * bf[j];
        }
        __syncthreads();
    }

    // ---- epilogue: alpha, per-row bias, scalar add ----
    #pragma unroll
    for (int i = 0; i < TM; i++) {
        const int m = bm + ty * TM + i;
        const float bv = (bias != nullptr ? bias[m] : 0.f) + addc;
        #pragma unroll
        for (int j = 0; j < TN; j += 4) {
            float4 o;
            o.x = alpha * acc[i][j + 0] + bv;
            o.y = alpha * acc[i][j + 1] + bv;
            o.z = alpha * acc[i][j + 2] + bv;
            o.w = alpha * acc[i][j + 3] + bv;
            *reinterpret_cast<float4*>(&C[(size_t)m * N + bn + tx * TN + j]) = o;
        }
    }
}

// ---------------------------------------------------------------------------
// Row softmax, in place. One block per row of 4096. Values stay in registers.
// ---------------------------------------------------------------------------
__global__ __launch_bounds__(256) void softmax_kernel(float* __restrict__ s)
{
    float4* r4 = reinterpret_cast<float4*>(s + (size_t)blockIdx.x * HW);

    float4 v[4];
    float mx = -1e30f;
    #pragma unroll
    for (int i = 0; i < 4; i++) {
        v[i] = r4[threadIdx.x + i * 256];
        mx = fmaxf(mx, fmaxf(fmaxf(v[i].x, v[i].y), fmaxf(v[i].z, v[i].w)));
    }

    __shared__ float red[256];
    red[threadIdx.x] = mx;
    __syncthreads();
    for (int off = 128; off > 0; off >>= 1) {
        if (threadIdx.x < off)
            red[threadIdx.x] = fmaxf(red[threadIdx.x], red[threadIdx.x + off]);
        __syncthreads();
    }
    mx = red[0];
    __syncthreads();

    float sum = 0.f;
    #pragma unroll
    for (int i = 0; i < 4; i++) {
        v[i].x = __expf(v[i].x - mx);
        v[i].y = __expf(v[i].y - mx);
        v[i].z = __expf(v[i].z - mx);
        v[i].w = __expf(v[i].w - mx);
        sum += v[i].x + v[i].y + v[i].z + v[i].w;
    }
    red[threadIdx.x] = sum;
    __syncthreads();
    for (int off = 128; off > 0; off >>= 1) {
        if (threadIdx.x < off)
            red[threadIdx.x] += red[threadIdx.x + off];
        __syncthreads();
    }
    const float inv = 1.f / red[0];

    #pragma unroll
    for (int i = 0; i < 4; i++) {
        v[i].x *= inv; v[i].y *= inv; v[i].z *= inv; v[i].w *= inv;
        r4[threadIdx.x + i * 256] = v[i];
    }
}

// ---------------------------------------------------------------------------
// Launch
// ---------------------------------------------------------------------------
extern "C" void kernel_launch(void* const* d_in, const int* in_sizes, int n_in,
                              void* d_out, int out_size)
{
    const float* x  = (const float*)d_in[0];
    const float* gs = (const float*)d_in[1];
    const float* gb = (const float*)d_in[2];
    const float* wq = (const float*)d_in[3];
    const float* bq = (const float*)d_in[4];
    const float* wk = (const float*)d_in[5];
    const float* bk = (const float*)d_in[6];
    const float* wv = (const float*)d_in[7];
    const float* bv = (const float*)d_in[8];
    const float* wp = (const float*)d_in[9];
    const float* bp = (const float*)d_in[10];
    float* out = (float*)d_out;

    float *xn, *q, *k, *v, *s, *o;
    cudaGetSymbolAddress((void**)&xn, g_xn);
    cudaGetSymbolAddress((void**)&q,  g_q);
    cudaGetSymbolAddress((void**)&k,  g_k);
    cudaGetSymbolAddress((void**)&v,  g_v);
    cudaGetSymbolAddress((void**)&s,  g_s);
    cudaGetSymbolAddress((void**)&o,  g_o);

    // 1) GroupNorm
    groupnorm_kernel<<<BATCH * NGRP, 256>>>(x, gs, gb, xn);

    // 2) Q/K/V 1x1 convs: C = W(512x512) @ xn(512x4096) + b, per batch
    dim3 gQKV(HW / BN, CH / BM, BATCH);   // (32, 4, 4)
    sgemm_kernel<false, false><<<gQKV, 256>>>(wq, xn, bq, q, CH, HW, CH, 1.f, 0.f, 0, CHW, CHW);
    sgemm_kernel<false, false><<<gQKV, 256>>>(wk, xn, bk, k, CH, HW, CH, 1.f, 0.f, 0, CHW, CHW);
    sgemm_kernel<false, false><<<gQKV, 256>>>(wv, xn, bv, v, CH, HW, CH, 1.f, 0.f, 0, CHW, CHW);

    // 3) scores = (q^T k) * C^-0.5 : M=N=4096, K=512, A=q (K-major), B=k
    const float alpha = 1.0f / sqrtf((float)CH);
    dim3 gS(HW / BN, HW / BM, BATCH);     // (32, 32, 4)
    sgemm_kernel<true, false><<<gS, 256>>>(q, k, nullptr, s, HW, HW, CH, alpha, 0.f, CHW, CHW, SHW);

    // 4) softmax over rows (in place)
    softmax_kernel<<<BATCH * HW, 256>>>(s);

    // 5) o = v @ attn^T : M=512, N=4096, K=4096, B stored row-major [i][j] -> TB
    dim3 gO(HW / BN, CH / BM, BATCH);     // (32, 4, 4)
    sgemm_kernel<false, true><<<gO, 256>>>(v, s, nullptr, o, CH, HW, HW, 1.f, 0.f, CHW, SHW, CHW);

    // 6) proj + bias + height scalar (64)
    sgemm_kernel<false, false><<<gQKV, 256>>>(wp, o, bp, out, CH, HW, CH, 1.f, 64.0f, 0, CHW, CHW);
}

// round 3
// speedup vs baseline: 5.5317x; 5.5317x over previous
#include <cuda_runtime.h>
#include <cuda_bf16.h>
#include <cstdint>
#include <math.h>

#define BATCH 4
#define CH    512
#define HW    4096
#define NGRP  32
#define CPG   16

static const size_t CHW = (size_t)CH * HW;
static const size_t SHW = (size_t)HW * HW;
#define CC (CH * CH)

// ---------------- scratch ----------------
__device__ __nv_bfloat16 g_xn [BATCH * CH * HW];   // [c, hw]
__device__ __nv_bfloat16 g_xnT[BATCH * CH * HW];   // [hw, c]
__device__ __nv_bfloat16 g_q  [BATCH * CH * HW];   // [hw, c]
__device__ __nv_bfloat16 g_k  [BATCH * CH * HW];   // [hw, c]
__device__ __nv_bfloat16 g_v  [BATCH * CH * HW];   // [c, hw]
__device__ float         g_s  [BATCH * HW * HW];   // fp32 scores
__device__ __nv_bfloat16 g_at [BATCH * HW * HW];   // bf16 attn
__device__ __nv_bfloat16 g_o  [BATCH * CH * HW];   // [c, hw]
__device__ __nv_bfloat16 g_oT [BATCH * CH * HW];   // [hw, c]
__device__ __nv_bfloat16 g_w  [4 * CH * CH];       // wq, wk, wv, wp

// ---------------- PTX helpers (family-portable: sm_80-era) ----------------
__device__ __forceinline__ uint32_t smem_u32(const void* p) {
    uint32_t a;
    asm("{ .reg .u64 t; cvta.to.shared.u64 t, %1; cvt.u32.u64 %0, t; }"
        : "=r"(a) : "l"(p));
    return a;
}
__device__ __forceinline__ void cp16(uint32_t s, const void* g) {
    asm volatile("cp.async.cg.shared.global [%0], [%1], 16;"
                 :: "r"(s), "l"(__cvta_generic_to_global(g)) : "memory");
}
#define CP_COMMIT() asm volatile("cp.async.commit_group;" ::: "memory")
#define CP_WAIT1()  asm volatile("cp.async.wait_group 1;"  ::: "memory")

__device__ __forceinline__ void ldsm_x4(uint32_t* r, uint32_t addr) {
    asm volatile("ldmatrix.sync.aligned.m8n8.x4.shared.b16 {%0,%1,%2,%3}, [%4];"
        : "=r"(r[0]), "=r"(r[1]), "=r"(r[2]), "=r"(r[3]) : "r"(addr));
}
__device__ __forceinline__ void mma16816(float* c, const uint32_t* a,
                                         uint32_t b0, uint32_t b1) {
    asm volatile(
        "mma.sync.aligned.m16n8k16.row.col.f32.bf16.bf16.f32 "
        "{%0,%1,%2,%3}, {%4,%5,%6,%7}, {%8,%9}, {%0,%1,%2,%3};"
        : "+f"(c[0]), "+f"(c[1]), "+f"(c[2]), "+f"(c[3])
        : "r"(a[0]), "r"(a[1]), "r"(a[2]), "r"(a[3]), "r"(b0), "r"(b1));
}

// ---------------------------------------------------------------------------
// GroupNorm -> bf16 [c, hw]
// ---------------------------------------------------------------------------
__global__ __launch_bounds__(256) void groupnorm_kernel(
    const float* __restrict__ x, const float* __restrict__ scale,
    const float* __restrict__ bias, __nv_bfloat16* __restrict__ xn)
{
    const int b = blockIdx.x / NGRP, g = blockIdx.x % NGRP;
    const size_t base = ((size_t)b * CH + (size_t)g * CPG) * HW;
    const int n4 = CPG * HW / 4;

    const float4* xin = reinterpret_cast<const float4*>(x + base);
    float s = 0.f, ss = 0.f;
    for (int i = threadIdx.x; i < n4; i += 256) {
        float4 t = xin[i];
        s  += t.x + t.y + t.z + t.w;
        ss += t.x * t.x + t.y * t.y + t.z * t.z + t.w * t.w;
    }
    __shared__ float r1[256], r2[256];
    r1[threadIdx.x] = s; r2[threadIdx.x] = ss;
    __syncthreads();
    for (int off = 128; off > 0; off >>= 1) {
        if (threadIdx.x < off) {
            r1[threadIdx.x] += r1[threadIdx.x + off];
            r2[threadIdx.x] += r2[threadIdx.x + off];
        }
        __syncthreads();
    }
    const float inv_n = 1.f / (float)(CPG * HW);
    const float mean = r1[0] * inv_n;
    const float var  = fmaxf(r2[0] * inv_n - mean * mean, 0.f);
    const float rstd = rsqrtf(var + 1e-6f);

    uint2* xo = reinterpret_cast<uint2*>(xn + base);
    for (int i = threadIdx.x; i < n4; i += 256) {
        const int c = g * CPG + (i >> 10);
        const float a = scale[c] * rstd;
        const float d = bias[c] - mean * a;
        float4 t = xin[i];
        __nv_bfloat162 h0 = __floats2bfloat162_rn(t.x * a + d, t.y * a + d);
        __nv_bfloat162 h1 = __floats2bfloat162_rn(t.z * a + d, t.w * a + d);
        uint2 o;
        o.x = *reinterpret_cast<uint32_t*>(&h0);
        o.y = *reinterpret_cast<uint32_t*>(&h1);
        xo[i] = o;
    }
}

// ---------------------------------------------------------------------------
// bf16 transpose [R, C] -> [C, R]
// ---------------------------------------------------------------------------
__global__ __launch_bounds__(256) void transpose_bf16(
    const __nv_bfloat16* __restrict__ in, __nv_bfloat16* __restrict__ out,
    int R, int C)
{
    __shared__ uint16_t tile[64][72];
    const size_t zoff = (size_t)blockIdx.z * (size_t)R * C;
    const int r0 = blockIdx.y * 64, c0 = blockIdx.x * 64;

    #pragma unroll
    for (int it = 0; it < 2; it++) {
        int idx = threadIdx.x + it * 256;
        int r = idx >> 3, c8 = idx & 7;
        uint4 v = *reinterpret_cast<const uint4*>(in + zoff + (size_t)(r0 + r) * C + c0 + c8 * 8);
        *reinterpret_cast<uint4*>(&tile[r][c8 * 8]) = v;
    }
    __syncthreads();
    #pragma unroll
    for (int it = 0; it < 2; it++) {
        int idx = threadIdx.x + it * 256;
        int c = idx >> 3, r8 = idx & 7;
        uint16_t tmp[8];
        #pragma unroll
        for (int i = 0; i < 8; i++) tmp[i] = tile[r8 * 8 + i][c];
        *reinterpret_cast<uint4*>(out + zoff + (size_t)(c0 + c) * R + r0 + r8 * 8) =
            *reinterpret_cast<uint4*>(tmp);
    }
}

// ---------------------------------------------------------------------------
// weights fp32 -> bf16
// ---------------------------------------------------------------------------
__global__ __launch_bounds__(256) void cvt_w_kernel(
    const float* __restrict__ a, const float* __restrict__ b,
    const float* __restrict__ c, const float* __restrict__ d,
    __nv_bfloat16* __restrict__ w)
{
    const int i = blockIdx.x * 256 + threadIdx.x;
    const float* s = (blockIdx.y == 0) ? a : (blockIdx.y == 1) ? b : (blockIdx.y == 2) ? c : d;
    w[(size_t)blockIdx.y * CC + i] = __float2bfloat16(s[i]);
}

// ---------------------------------------------------------------------------
// bf16 HMMA GEMM: D[M,N] = alpha * A[M,K] @ B[N,K]^T + bias_m + bias_n + addc
// BM=BN=128, BK=32, 3-stage cp.async, 8 warps (4Mx2N), warp tile 32x64.
// Smem rows padded to 80 B for conflict-free ldmatrix.
// ---------------------------------------------------------------------------
#define PITCH  80
#define STG_SZ 20480          // 2 * 128 * 80
#define NSTG   3
#define GEMM_SMEM (NSTG * STG_SZ)   // 61440

template<bool OUT_BF16>
__global__ __launch_bounds__(256) void gemm_bf16(
    const __nv_bfloat16* __restrict__ A,
    const __nv_bfloat16* __restrict__ B,
    void* __restrict__ Cout,
    const float* __restrict__ bias_m,
    const float* __restrict__ bias_n,
    int M, int N, int K,
    float alpha, float addc,
    size_t sA, size_t sB, size_t sC)
{
    extern __shared__ __align__(16) char smem[];
    const uint32_t sb = smem_u32(smem);

    const int tid  = threadIdx.x;
    const int lane = tid & 31;
    const int wid  = tid >> 5;
    const int wm   = wid >> 1;              // 0..3
    const int wn   = wid & 1;               // 0..1
    const int bm = blockIdx.y * 128;
    const int bn = blockIdx.x * 128;

    const __nv_bfloat16* Ab = A + (size_t)blockIdx.z * sA + (size_t)bm * K;
    const __nv_bfloat16* Bb = B + (size_t)blockIdx.z * sB + (size_t)bn * K;

    // per-thread cp.async slots (2 x 16B for A, 2 for B per stage)
    int row0 = tid >> 2,            c0 = tid & 3;
    int row1 = (tid + 256) >> 2,    c1 = (tid + 256) & 3;
    const uint32_t so0 = (uint32_t)row0 * PITCH + c0 * 16;
    const uint32_t so1 = (uint32_t)row1 * PITCH + c1 * 16;

    const int nk = K >> 5;

    // prologue: stages 0,1
    #pragma unroll
    for (int s = 0; s < 2; s++) {
        const int koff = s << 5;
        const uint32_t st = sb + s * STG_SZ;
        cp16(st + so0,          Ab + (size_t)row0 * K + koff + c0 * 8);
        cp16(st + so1,          Ab + (size_t)row1 * K + koff + c1 * 8);
        cp16(st + 10240 + so0,  Bb + (size_t)row0 * K + koff + c0 * 8);
        cp16(st + 10240 + so1,  Bb + (size_t)row1 * K + koff + c1 * 8);
        CP_COMMIT();
    }

    float acc[2][8][4];
    #pragma unroll
    for (int i = 0; i < 2; i++)
        #pragma unroll
        for (int j = 0; j < 8; j++)
            #pragma unroll
            for (int t = 0; t < 4; t++) acc[i][j][t] = 0.f;

    const uint32_t lrow = lane & 15;         // ldmatrix row select
    const uint32_t lsel = (lane >> 4) * 16;  // k-half byte select

    int buf = 0;
    for (int ck = 0; ck < nk; ck++) {
        CP_WAIT1();
        __syncthreads();

        // issue load for ck+2 into (buf+2)%3
        if (ck + 2 < nk) {
            const int koff = (ck + 2) << 5;
            const uint32_t st = sb + ((buf + 2) % NSTG) * STG_SZ;
            cp16(st + so0,          Ab + (size_t)row0 * K + koff + c0 * 8);
            cp16(st + so1,          Ab + (size_t)row1 * K + koff + c1 * 8);
            cp16(st + 10240 + so0,  Bb + (size_t)row0 * K + koff + c0 * 8);
            cp16(st + 10240 + so1,  Bb + (size_t)row1 * K + koff + c1 * 8);
        }
        CP_COMMIT();

        const uint32_t sa = sb + buf * STG_SZ;
        const uint32_t sbm = sa + 10240;
        #pragma unroll
        for (int kf = 0; kf < 2; kf++) {
            uint32_t ar[2][4];
            #pragma unroll
            for (int mi = 0; mi < 2; mi++)
                ldsm_x4(ar[mi], sa + (wm * 32 + mi * 16 + lrow) * PITCH + kf * 32 + lsel);
            uint32_t br[4][4];
            #pragma unroll
            for (int nb = 0; nb < 4; nb++)
                ldsm_x4(br[nb], sbm + (wn * 64 + nb * 16 + lrow) * PITCH + kf * 32 + lsel);
            #pragma unroll
            for (int mi = 0; mi < 2; mi++)
                #pragma unroll
                for (int nj = 0; nj < 8; nj++) {
                    const int nb = nj >> 1, od = nj & 1;
                    mma16816(acc[mi][nj], ar[mi], br[nb][od], br[nb][od + 2]);
                }
        }
        buf = (buf + 1) % NSTG;
        __syncthreads();
    }

    // ---- epilogue ----
    const int gid = lane >> 2, tig = lane & 3;
    #pragma unroll
    for (int mi = 0; mi < 2; mi++) {
        #pragma unroll
        for (int r2 = 0; r2 < 2; r2++) {
            const int m = bm + wm * 32 + mi * 16 + gid + r2 * 8;
            const float bmv = (bias_m ? bias_m[m] : 0.f) + addc;
            #pragma unroll
            for (int nj = 0; nj < 8; nj++) {
                const int n = bn + wn * 64 + nj * 8 + tig * 2;
                float x0 = acc[mi][nj][r2 * 2]     * alpha + bmv;
                float x1 = acc[mi][nj][r2 * 2 + 1] * alpha + bmv;
                if (bias_n) { x0 += bias_n[n]; x1 += bias_n[n + 1]; }
                if (OUT_BF16) {
                    __nv_bfloat162 h = __floats2bfloat162_rn(x0, x1);
                    *reinterpret_cast<uint32_t*>(
                        (__nv_bfloat16*)Cout + (size_t)blockIdx.z * sC + (size_t)m * N + n)
                        = *reinterpret_cast<uint32_t*>(&h);
                } else {
                    float2 o = make_float2(x0, x1);
                    *reinterpret_cast<float2*>(
                        (float*)Cout + (size_t)blockIdx.z * sC + (size_t)m * N + n) = o;
                }
            }
        }
    }
}

// ---------------------------------------------------------------------------
// Row softmax: fp32 in -> bf16 out
// ---------------------------------------------------------------------------
__global__ __launch_bounds__(256) void softmax_kernel(
    const float* __restrict__ s, __nv_bfloat16* __restrict__ at)
{
    const float4* r4 = reinterpret_cast<const float4*>(s + (size_t)blockIdx.x * HW);
    uint2* o4 = reinterpret_cast<uint2*>(at + (size_t)blockIdx.x * HW);

    float4 v[4];
    float mx = -1e30f;
    #pragma unroll
    for (int i = 0; i < 4; i++) {
        v[i] = r4[threadIdx.x + i * 256];
        mx = fmaxf(mx, fmaxf(fmaxf(v[i].x, v[i].y), fmaxf(v[i].z, v[i].w)));
    }
    __shared__ float red[256];
    red[threadIdx.x] = mx;
    __syncthreads();
    for (int off = 128; off > 0; off >>= 1) {
        if (threadIdx.x < off)
            red[threadIdx.x] = fmaxf(red[threadIdx.x], red[threadIdx.x + off]);
        __syncthreads();
    }
    mx = red[0];
    __syncthreads();

    float sum = 0.f;
    #pragma unroll
    for (int i = 0; i < 4; i++) {
        v[i].x = __expf(v[i].x - mx); v[i].y = __expf(v[i].y - mx);
        v[i].z = __expf(v[i].z - mx); v[i].w = __expf(v[i].w - mx);
        sum += v[i].x + v[i].y + v[i].z + v[i].w;
    }
    red[threadIdx.x] = sum;
    __syncthreads();
    for (int off = 128; off > 0; off >>= 1) {
        if (threadIdx.x < off) red[threadIdx.x] += red[threadIdx.x + off];
        __syncthreads();
    }
    const float inv = 1.f / red[0];

    #pragma unroll
    for (int i = 0; i < 4; i++) {
        __nv_bfloat162 h0 = __floats2bfloat162_rn(v[i].x * inv, v[i].y * inv);
        __nv_bfloat162 h1 = __floats2bfloat162_rn(v[i].z * inv, v[i].w * inv);
        uint2 o;
        o.x = *reinterpret_cast<uint32_t*>(&h0);
        o.y = *reinterpret_cast<uint32_t*>(&h1);
        o4[threadIdx.x + i * 256] = o;
    }
}

// ---------------------------------------------------------------------------
// Launch
// ---------------------------------------------------------------------------
extern "C" void kernel_launch(void* const* d_in, const int* in_sizes, int n_in,
                              void* d_out, int out_size)
{
    const float* x  = (const float*)d_in[0];
    const float* gs = (const float*)d_in[1];
    const float* gb = (const float*)d_in[2];
    const float* wq = (const float*)d_in[3];
    const float* bq = (const float*)d_in[4];
    const float* wk = (const float*)d_in[5];
    const float* bk = (const float*)d_in[6];
    const float* wv = (const float*)d_in[7];
    const float* bv = (const float*)d_in[8];
    const float* wp = (const float*)d_in[9];
    const float* bp = (const float*)d_in[10];
    float* out = (float*)d_out;

    __nv_bfloat16 *xn, *xnT, *q, *k, *v, *at, *o, *oT, *w;
    float* s;
    cudaGetSymbolAddress((void**)&xn,  g_xn);
    cudaGetSymbolAddress((void**)&xnT, g_xnT);
    cudaGetSymbolAddress((void**)&q,   g_q);
    cudaGetSymbolAddress((void**)&k,   g_k);
    cudaGetSymbolAddress((void**)&v,   g_v);
    cudaGetSymbolAddress((void**)&s,   g_s);
    cudaGetSymbolAddress((void**)&at,  g_at);
    cudaGetSymbolAddress((void**)&o,   g_o);
    cudaGetSymbolAddress((void**)&oT,  g_oT);
    cudaGetSymbolAddress((void**)&w,   g_w);

    cudaFuncSetAttribute(gemm_bf16<true>,  cudaFuncAttributeMaxDynamicSharedMemorySize, GEMM_SMEM);
    cudaFuncSetAttribute(gemm_bf16<false>, cudaFuncAttributeMaxDynamicSharedMemorySize, GEMM_SMEM);

    // 0) weights -> bf16
    cvt_w_kernel<<<dim3(CC / 256, 4), 256>>>(wq, wk, wv, wp, w);

    // 1) GroupNorm
    groupnorm_kernel<<<BATCH * NGRP, 256>>>(x, gs, gb, xn);

    // 2) transpose xn -> xnT [hw, c]
    transpose_bf16<<<dim3(HW / 64, CH / 64, BATCH), 256>>>(xn, xnT, CH, HW);

    // 3) Q, K: [hw, co] = xnT @ W^T + b  (bias over N)
    dim3 gQK(CH / 128, HW / 128, BATCH);
    gemm_bf16<true><<<gQK, 256, GEMM_SMEM>>>(xnT, w,      q, nullptr, bq, HW, CH, CH, 1.f, 0.f, CHW, 0, CHW);
    gemm_bf16<true><<<gQK, 256, GEMM_SMEM>>>(xnT, w + CC, k, nullptr, bk, HW, CH, CH, 1.f, 0.f, CHW, 0, CHW);

    // 4) V: [co, hw] = Wv @ xnT^T + b  (bias over M)
    dim3 gV(HW / 128, CH / 128, BATCH);
    gemm_bf16<true><<<gV, 256, GEMM_SMEM>>>(w + 2 * CC, xnT, v, bv, nullptr, CH, HW, CH, 1.f, 0.f, 0, CHW, CHW);

    // 5) scores fp32
    const float alpha = 1.0f / sqrtf((float)CH);
    dim3 gS(HW / 128, HW / 128, BATCH);
    gemm_bf16<false><<<gS, 256, GEMM_SMEM>>>(q, k, s, nullptr, nullptr, HW, HW, CH, alpha, 0.f, CHW, CHW, SHW);

    // 6) softmax -> bf16 attn
    softmax_kernel<<<BATCH * HW, 256>>>(s, at);

    // 7) o[c, i] = v[c, :] . attn[i, :]
    gemm_bf16<true><<<gV, 256, GEMM_SMEM>>>(v, at, o, nullptr, nullptr, CH, HW, HW, 1.f, 0.f, CHW, SHW, CHW);

    // 8) transpose o -> oT
    transpose_bf16<<<dim3(HW / 64, CH / 64, BATCH), 256>>>(o, oT, CH, HW);

    // 9) proj fp32 + bias + 64
    gemm_bf16<false><<<gV, 256, GEMM_SMEM>>>(w + 3 * CC, oT, out, bp, nullptr, CH, HW, CH, 1.f, 64.0f, 0, CHW, CHW);
}

// round 4
// speedup vs baseline: 6.0745x; 1.0981x over previous
#include <cuda_runtime.h>
#include <cuda_bf16.h>
#include <cstdint>
#include <math.h>

#define BATCH 4
#define CH    512
#define HW    4096
#define NGRP  32
#define CPG   16

static const size_t CHW = (size_t)CH * HW;
static const size_t SHW = (size_t)HW * HW;
#define CC (CH * CH)

// ---------------- scratch ----------------
__device__ __nv_bfloat16 g_xn [BATCH * CH * HW];   // [c, hw]
__device__ __nv_bfloat16 g_xnT[BATCH * CH * HW];   // [hw, c]
__device__ __nv_bfloat16 g_q  [BATCH * CH * HW];   // [hw, c]
__device__ __nv_bfloat16 g_k  [BATCH * CH * HW];   // [hw, c]
__device__ __nv_bfloat16 g_v  [BATCH * CH * HW];   // [c, hw]
__device__ __nv_bfloat16 g_s  [BATCH * HW * HW];   // bf16 scores (128 MB)
__device__ __nv_bfloat16 g_at [BATCH * HW * HW];   // bf16 attn   (128 MB)
__device__ __nv_bfloat16 g_o  [BATCH * CH * HW];   // [c, hw]
__device__ __nv_bfloat16 g_oT [BATCH * CH * HW];   // [hw, c]
__device__ __nv_bfloat16 g_w  [4 * CH * CH];       // wq, wk, wv, wp

// ---------------- PTX helpers (family-portable sm_80-era) ----------------
__device__ __forceinline__ uint32_t smem_u32(const void* p) {
    uint32_t a;
    asm("{ .reg .u64 t; cvta.to.shared.u64 t, %1; cvt.u32.u64 %0, t; }"
        : "=r"(a) : "l"(p));
    return a;
}
__device__ __forceinline__ void cp16(uint32_t s, const void* g) {
    asm volatile("cp.async.cg.shared.global [%0], [%1], 16;"
                 :: "r"(s), "l"(__cvta_generic_to_global(g)) : "memory");
}
#define CP_COMMIT() asm volatile("cp.async.commit_group;" ::: "memory")
#define CP_WAIT1()  asm volatile("cp.async.wait_group 1;"  ::: "memory")

__device__ __forceinline__ void ldsm_x4(uint32_t* r, uint32_t addr) {
    asm volatile("ldmatrix.sync.aligned.m8n8.x4.shared.b16 {%0,%1,%2,%3}, [%4];"
        : "=r"(r[0]), "=r"(r[1]), "=r"(r[2]), "=r"(r[3]) : "r"(addr));
}
__device__ __forceinline__ void mma16816(float* c, const uint32_t* a,
                                         uint32_t b0, uint32_t b1) {
    asm volatile(
        "mma.sync.aligned.m16n8k16.row.col.f32.bf16.bf16.f32 "
        "{%0,%1,%2,%3}, {%4,%5,%6,%7}, {%8,%9}, {%0,%1,%2,%3};"
        : "+f"(c[0]), "+f"(c[1]), "+f"(c[2]), "+f"(c[3])
        : "r"(a[0]), "r"(a[1]), "r"(a[2]), "r"(a[3]), "r"(b0), "r"(b1));
}

// ---------------------------------------------------------------------------
// GroupNorm -> bf16 [c, hw]
// ---------------------------------------------------------------------------
__global__ __launch_bounds__(256) void groupnorm_kernel(
    const float* __restrict__ x, const float* __restrict__ scale,
    const float* __restrict__ bias, __nv_bfloat16* __restrict__ xn)
{
    const int b = blockIdx.x / NGRP, g = blockIdx.x % NGRP;
    const size_t base = ((size_t)b * CH + (size_t)g * CPG) * HW;
    const int n4 = CPG * HW / 4;

    const float4* xin = reinterpret_cast<const float4*>(x + base);
    float s = 0.f, ss = 0.f;
    for (int i = threadIdx.x; i < n4; i += 256) {
        float4 t = xin[i];
        s  += t.x + t.y + t.z + t.w;
        ss += t.x * t.x + t.y * t.y + t.z * t.z + t.w * t.w;
    }
    __shared__ float r1[256], r2[256];
    r1[threadIdx.x] = s; r2[threadIdx.x] = ss;
    __syncthreads();
    for (int off = 128; off > 0; off >>= 1) {
        if (threadIdx.x < off) {
            r1[threadIdx.x] += r1[threadIdx.x + off];
            r2[threadIdx.x] += r2[threadIdx.x + off];
        }
        __syncthreads();
    }
    const float inv_n = 1.f / (float)(CPG * HW);
    const float mean = r1[0] * inv_n;
    const float var  = fmaxf(r2[0] * inv_n - mean * mean, 0.f);
    const float rstd = rsqrtf(var + 1e-6f);

    uint2* xo = reinterpret_cast<uint2*>(xn + base);
    for (int i = threadIdx.x; i < n4; i += 256) {
        const int c = g * CPG + (i >> 10);
        const float a = scale[c] * rstd;
        const float d = bias[c] - mean * a;
        float4 t = xin[i];
        __nv_bfloat162 h0 = __floats2bfloat162_rn(t.x * a + d, t.y * a + d);
        __nv_bfloat162 h1 = __floats2bfloat162_rn(t.z * a + d, t.w * a + d);
        uint2 o;
        o.x = *reinterpret_cast<uint32_t*>(&h0);
        o.y = *reinterpret_cast<uint32_t*>(&h1);
        xo[i] = o;
    }
}

// ---------------------------------------------------------------------------
// bf16 transpose [R, C] -> [C, R]
// ---------------------------------------------------------------------------
__global__ __launch_bounds__(256) void transpose_bf16(
    const __nv_bfloat16* __restrict__ in, __nv_bfloat16* __restrict__ out,
    int R, int C)
{
    __shared__ uint16_t tile[64][72];
    const size_t zoff = (size_t)blockIdx.z * (size_t)R * C;
    const int r0 = blockIdx.y * 64, c0 = blockIdx.x * 64;

    #pragma unroll
    for (int it = 0; it < 2; it++) {
        int idx = threadIdx.x + it * 256;
        int r = idx >> 3, c8 = idx & 7;
        uint4 v = *reinterpret_cast<const uint4*>(in + zoff + (size_t)(r0 + r) * C + c0 + c8 * 8);
        *reinterpret_cast<uint4*>(&tile[r][c8 * 8]) = v;
    }
    __syncthreads();
    #pragma unroll
    for (int it = 0; it < 2; it++) {
        int idx = threadIdx.x + it * 256;
        int c = idx >> 3, r8 = idx & 7;
        uint16_t tmp[8];
        #pragma unroll
        for (int i = 0; i < 8; i++) tmp[i] = tile[r8 * 8 + i][c];
        *reinterpret_cast<uint4*>(out + zoff + (size_t)(c0 + c) * R + r0 + r8 * 8) =
            *reinterpret_cast<uint4*>(tmp);
    }
}

// ---------------------------------------------------------------------------
// weights fp32 -> bf16
// ---------------------------------------------------------------------------
__global__ __launch_bounds__(256) void cvt_w_kernel(
    const float* __restrict__ a, const float* __restrict__ b,
    const float* __restrict__ c, const float* __restrict__ d,
    __nv_bfloat16* __restrict__ w)
{
    const int i = blockIdx.x * 256 + threadIdx.x;
    const float* s = (blockIdx.y == 0) ? a : (blockIdx.y == 1) ? b : (blockIdx.y == 2) ? c : d;
    w[(size_t)blockIdx.y * CC + i] = __float2bfloat16(s[i]);
}

// ---------------------------------------------------------------------------
// bf16 HMMA GEMM: D[M,N] = alpha * A[M,K] @ B[N,K]^T + bias_m + bias_n + addc
// BM=BN=128, BK=64, 3-stage cp.async, 8 warps (4Mx2N), warp tile 32x64.
// Smem rows padded to 144 B (conflict-free ldmatrix). ONE barrier per chunk.
// ---------------------------------------------------------------------------
#define PITCH  144
#define OPSZ   18432           // 128 * 144
#define STG_SZ 36864           // 2 * OPSZ
#define NSTG   3
#define GEMM_SMEM (NSTG * STG_SZ)   // 110592

template<bool OUT_BF16>
__global__ void __launch_bounds__(256, 2) gemm_bf16(
    const __nv_bfloat16* __restrict__ A,
    const __nv_bfloat16* __restrict__ B,
    void* __restrict__ Cout,
    const float* __restrict__ bias_m,
    const float* __restrict__ bias_n,
    int M, int N, int K,
    float alpha, float addc,
    size_t sA, size_t sB, size_t sC)
{
    extern __shared__ __align__(16) char smem[];
    const uint32_t sb = smem_u32(smem);

    const int tid  = threadIdx.x;
    const int lane = tid & 31;
    const int wid  = tid >> 5;
    const int wm   = wid >> 1;              // 0..3
    const int wn   = wid & 1;               // 0..1
    const int bm = blockIdx.y * 128;
    const int bn = blockIdx.x * 128;

    const __nv_bfloat16* Ab = A + (size_t)blockIdx.z * sA + (size_t)bm * K;
    const __nv_bfloat16* Bb = B + (size_t)blockIdx.z * sB + (size_t)bn * K;

    // cp.async slots: 4 x 16B per operand per thread per stage
    int rr[4], cc[4];
    uint32_t so[4];
    #pragma unroll
    for (int j = 0; j < 4; j++) {
        const int idx = tid + j * 256;      // 0..1023
        rr[j] = idx >> 3;                   // row 0..127
        cc[j] = idx & 7;                    // 16B-chunk 0..7
        so[j] = (uint32_t)rr[j] * PITCH + cc[j] * 16;
    }

    const int nk = K >> 6;

    // prologue: stages 0,1
    #pragma unroll
    for (int s = 0; s < 2; s++) {
        const int koff = s << 6;
        const uint32_t st = sb + s * STG_SZ;
        #pragma unroll
        for (int j = 0; j < 4; j++) {
            cp16(st + so[j],        Ab + (size_t)rr[j] * K + koff + cc[j] * 8);
            cp16(st + OPSZ + so[j], Bb + (size_t)rr[j] * K + koff + cc[j] * 8);
        }
        CP_COMMIT();
    }

    float acc[2][8][4];
    #pragma unroll
    for (int i = 0; i < 2; i++)
        #pragma unroll
        for (int j = 0; j < 8; j++)
            #pragma unroll
            for (int t = 0; t < 4; t++) acc[i][j][t] = 0.f;

    const uint32_t lrow = lane & 15;
    const uint32_t lsel = (lane >> 4) * 16;

    int buf = 0;
    for (int ck = 0; ck < nk; ck++) {
        CP_WAIT1();
        __syncthreads();

        if (ck + 2 < nk) {
            const int koff = (ck + 2) << 6;
            const uint32_t st = sb + ((buf + 2) % NSTG) * STG_SZ;
            #pragma unroll
            for (int j = 0; j < 4; j++) {
                cp16(st + so[j],        Ab + (size_t)rr[j] * K + koff + cc[j] * 8);
                cp16(st + OPSZ + so[j], Bb + (size_t)rr[j] * K + koff + cc[j] * 8);
            }
        }
        CP_COMMIT();

        const uint32_t sa  = sb + buf * STG_SZ;
        const uint32_t sbm = sa + OPSZ;
        #pragma unroll
        for (int kf = 0; kf < 4; kf++) {
            const uint32_t kofs = kf * 32 + lsel;
            uint32_t ar[2][4];
            #pragma unroll
            for (int mi = 0; mi < 2; mi++)
                ldsm_x4(ar[mi], sa + (wm * 32 + mi * 16 + lrow) * PITCH + kofs);
            uint32_t br[4][4];
            #pragma unroll
            for (int nb = 0; nb < 4; nb++)
                ldsm_x4(br[nb], sbm + (wn * 64 + nb * 16 + lrow) * PITCH + kofs);
            #pragma unroll
            for (int mi = 0; mi < 2; mi++)
                #pragma unroll
                for (int nj = 0; nj < 8; nj++) {
                    const int nb = nj >> 1, od = nj & 1;
                    mma16816(acc[mi][nj], ar[mi], br[nb][od], br[nb][od + 2]);
                }
        }
        buf = (buf + 1) % NSTG;
        // no trailing barrier: writes at iter ck target buffer (ck+2)%3,
        // whose readers finished before this iteration's leading barrier.
    }

    // ---- epilogue ----
    const int gid = lane >> 2, tig = lane & 3;
    #pragma unroll
    for (int mi = 0; mi < 2; mi++) {
        #pragma unroll
        for (int r2 = 0; r2 < 2; r2++) {
            const int m = bm + wm * 32 + mi * 16 + gid + r2 * 8;
            const float bmv = (bias_m ? bias_m[m] : 0.f) + addc;
            #pragma unroll
            for (int nj = 0; nj < 8; nj++) {
                const int n = bn + wn * 64 + nj * 8 + tig * 2;
                float x0 = acc[mi][nj][r2 * 2]     * alpha + bmv;
                float x1 = acc[mi][nj][r2 * 2 + 1] * alpha + bmv;
                if (bias_n) { x0 += bias_n[n]; x1 += bias_n[n + 1]; }
                if (OUT_BF16) {
                    __nv_bfloat162 h = __floats2bfloat162_rn(x0, x1);
                    *reinterpret_cast<uint32_t*>(
                        (__nv_bfloat16*)Cout + (size_t)blockIdx.z * sC + (size_t)m * N + n)
                        = *reinterpret_cast<uint32_t*>(&h);
                } else {
                    float2 o = make_float2(x0, x1);
                    *reinterpret_cast<float2*>(
                        (float*)Cout + (size_t)blockIdx.z * sC + (size_t)m * N + n) = o;
                }
            }
        }
    }
}

// ---------------------------------------------------------------------------
// Row softmax: bf16 in -> bf16 out. One block per row of 4096.
// ---------------------------------------------------------------------------
__global__ __launch_bounds__(256) void softmax_kernel(
    const __nv_bfloat16* __restrict__ s, __nv_bfloat16* __restrict__ at)
{
    const uint4* r4 = reinterpret_cast<const uint4*>(s + (size_t)blockIdx.x * HW);
    uint4* o4 = reinterpret_cast<uint4*>(at + (size_t)blockIdx.x * HW);

    float v[16];
    #pragma unroll
    for (int i = 0; i < 2; i++) {
        uint4 t = r4[threadIdx.x + i * 256];
        const uint32_t* u = reinterpret_cast<const uint32_t*>(&t);
        #pragma unroll
        for (int j = 0; j < 4; j++) {
            __nv_bfloat162 h = *reinterpret_cast<const __nv_bfloat162*>(&u[j]);
            float2 f = __bfloat1622float2(h);
            v[i * 8 + j * 2]     = f.x;
            v[i * 8 + j * 2 + 1] = f.y;
        }
    }
    float mx = -1e30f;
    #pragma unroll
    for (int i = 0; i < 16; i++) mx = fmaxf(mx, v[i]);

    __shared__ float red[256];
    red[threadIdx.x] = mx;
    __syncthreads();
    for (int off = 128; off > 0; off >>= 1) {
        if (threadIdx.x < off)
            red[threadIdx.x] = fmaxf(red[threadIdx.x], red[threadIdx.x + off]);
        __syncthreads();
    }
    mx = red[0];
    __syncthreads();

    float sum = 0.f;
    #pragma unroll
    for (int i = 0; i < 16; i++) { v[i] = __expf(v[i] - mx); sum += v[i]; }
    red[threadIdx.x] = sum;
    __syncthreads();
    for (int off = 128; off > 0; off >>= 1) {
        if (threadIdx.x < off) red[threadIdx.x] += red[threadIdx.x + off];
        __syncthreads();
    }
    const float inv = 1.f / red[0];

    #pragma unroll
    for (int i = 0; i < 2; i++) {
        uint4 t;
        uint32_t* u = reinterpret_cast<uint32_t*>(&t);
        #pragma unroll
        for (int j = 0; j < 4; j++) {
            __nv_bfloat162 h = __floats2bfloat162_rn(v[i * 8 + j * 2] * inv,
                                                     v[i * 8 + j * 2 + 1] * inv);
            u[j] = *reinterpret_cast<uint32_t*>(&h);
        }
        o4[threadIdx.x + i * 256] = t;
    }
}

// ---------------------------------------------------------------------------
// Launch
// ---------------------------------------------------------------------------
extern "C" void kernel_launch(void* const* d_in, const int* in_sizes, int n_in,
                              void* d_out, int out_size)
{
    const float* x  = (const float*)d_in[0];
    const float* gs = (const float*)d_in[1];
    const float* gb = (const float*)d_in[2];
    const float* wq = (const float*)d_in[3];
    const float* bq = (const float*)d_in[4];
    const float* wk = (const float*)d_in[5];
    const float* bk = (const float*)d_in[6];
    const float* wv = (const float*)d_in[7];
    const float* bv = (const float*)d_in[8];
    const float* wp = (const float*)d_in[9];
    const float* bp = (const float*)d_in[10];
    float* out = (float*)d_out;

    __nv_bfloat16 *xn, *xnT, *q, *k, *v, *s, *at, *o, *oT, *w;
    cudaGetSymbolAddress((void**)&xn,  g_xn);
    cudaGetSymbolAddress((void**)&xnT, g_xnT);
    cudaGetSymbolAddress((void**)&q,   g_q);
    cudaGetSymbolAddress((void**)&k,   g_k);
    cudaGetSymbolAddress((void**)&v,   g_v);
    cudaGetSymbolAddress((void**)&s,   g_s);
    cudaGetSymbolAddress((void**)&at,  g_at);
    cudaGetSymbolAddress((void**)&o,   g_o);
    cudaGetSymbolAddress((void**)&oT,  g_oT);
    cudaGetSymbolAddress((void**)&w,   g_w);

    cudaFuncSetAttribute(gemm_bf16<true>,  cudaFuncAttributeMaxDynamicSharedMemorySize, GEMM_SMEM);
    cudaFuncSetAttribute(gemm_bf16<false>, cudaFuncAttributeMaxDynamicSharedMemorySize, GEMM_SMEM);

    // 0) weights -> bf16
    cvt_w_kernel<<<dim3(CC / 256, 4), 256>>>(wq, wk, wv, wp, w);

    // 1) GroupNorm
    groupnorm_kernel<<<BATCH * NGRP, 256>>>(x, gs, gb, xn);

    // 2) transpose xn -> xnT [hw, c]
    transpose_bf16<<<dim3(HW / 64, CH / 64, BATCH), 256>>>(xn, xnT, CH, HW);

    // 3) Q, K: [hw, co] = xnT @ W^T + b  (bias over N)
    dim3 gQK(CH / 128, HW / 128, BATCH);
    gemm_bf16<true><<<gQK, 256, GEMM_SMEM>>>(xnT, w,      q, nullptr, bq, HW, CH, CH, 1.f, 0.f, CHW, 0, CHW);
    gemm_bf16<true><<<gQK, 256, GEMM_SMEM>>>(xnT, w + CC, k, nullptr, bk, HW, CH, CH, 1.f, 0.f, CHW, 0, CHW);

    // 4) V: [co, hw] = Wv @ xnT^T + b  (bias over M)
    dim3 gV(HW / 128, CH / 128, BATCH);
    gemm_bf16<true><<<gV, 256, GEMM_SMEM>>>(w + 2 * CC, xnT, v, bv, nullptr, CH, HW, CH, 1.f, 0.f, 0, CHW, CHW);

    // 5) scores -> bf16
    const float alpha = 1.0f / sqrtf((float)CH);
    dim3 gS(HW / 128, HW / 128, BATCH);
    gemm_bf16<true><<<gS, 256, GEMM_SMEM>>>(q, k, s, nullptr, nullptr, HW, HW, CH, alpha, 0.f, CHW, CHW, SHW);

    // 6) softmax -> bf16 attn
    softmax_kernel<<<BATCH * HW, 256>>>(s, at);

    // 7) o[c, i] = v[c, :] . attn[i, :]
    gemm_bf16<true><<<gV, 256, GEMM_SMEM>>>(v, at, o, nullptr, nullptr, CH, HW, HW, 1.f, 0.f, CHW, SHW, CHW);

    // 8) transpose o -> oT
    transpose_bf16<<<dim3(HW / 64, CH / 64, BATCH), 256>>>(o, oT, CH, HW);

    // 9) proj fp32 + bias + 64
    gemm_bf16<false><<<gV, 256, GEMM_SMEM>>>(w + 3 * CC, oT, out, bp, nullptr, CH, HW, CH, 1.f, 64.0f, 0, CHW, CHW);
}

// round 5
// speedup vs baseline: 6.4511x; 1.0620x over previous
#include <cuda_runtime.h>
#include <cuda_bf16.h>
#include <cuda_fp8.h>
#include <cstdint>
#include <math.h>

#define BATCH 4
#define CH    512
#define HW    4096
#define NGRP  32
#define CPG   16

static const size_t CHW = (size_t)CH * HW;
static const size_t SHW = (size_t)HW * HW;
#define CC (CH * CH)

// ---------------- scratch ----------------
__device__ __nv_bfloat16 g_xn [BATCH * CH * HW];   // [c, hw] bf16
__device__ __nv_bfloat16 g_xnT[BATCH * CH * HW];   // [hw, c] bf16
__device__ uint8_t       g_q  [BATCH * CH * HW];   // [hw, c] fp8
__device__ uint8_t       g_k  [BATCH * CH * HW];   // [hw, c] fp8
__device__ uint8_t       g_v  [BATCH * CH * HW];   // [c, hw] fp8
__device__ __nv_bfloat16 g_s  [BATCH * HW * HW];   // bf16 scores (128 MB)
__device__ uint8_t       g_at [BATCH * HW * HW];   // fp8 attn*256 (64 MB)
__device__ __nv_bfloat16 g_o2 [BATCH * CH * HW];   // [hw, c] bf16
__device__ __nv_bfloat16 g_w  [4 * CH * CH];       // wq, wk, wv, wp bf16

// ---------------- PTX helpers (family-portable) ----------------
__device__ __forceinline__ uint32_t smem_u32(const void* p) {
    uint32_t a;
    asm("{ .reg .u64 t; cvta.to.shared.u64 t, %1; cvt.u32.u64 %0, t; }"
        : "=r"(a) : "l"(p));
    return a;
}
__device__ __forceinline__ void cp16(uint32_t s, const void* g) {
    asm volatile("cp.async.cg.shared.global [%0], [%1], 16;"
                 :: "r"(s), "l"(__cvta_generic_to_global(g)) : "memory");
}
#define CP_COMMIT() asm volatile("cp.async.commit_group;" ::: "memory")
#define CP_WAIT1()  asm volatile("cp.async.wait_group 1;"  ::: "memory")

__device__ __forceinline__ void ldsm_x4(uint32_t* r, uint32_t addr) {
    asm volatile("ldmatrix.sync.aligned.m8n8.x4.shared.b16 {%0,%1,%2,%3}, [%4];"
        : "=r"(r[0]), "=r"(r[1]), "=r"(r[2]), "=r"(r[3]) : "r"(addr));
}
__device__ __forceinline__ void mma16816(float* c, const uint32_t* a,
                                         uint32_t b0, uint32_t b1) {
    asm volatile(
        "mma.sync.aligned.m16n8k16.row.col.f32.bf16.bf16.f32 "
        "{%0,%1,%2,%3}, {%4,%5,%6,%7}, {%8,%9}, {%0,%1,%2,%3};"
        : "+f"(c[0]), "+f"(c[1]), "+f"(c[2]), "+f"(c[3])
        : "r"(a[0]), "r"(a[1]), "r"(a[2]), "r"(a[3]), "r"(b0), "r"(b1));
}
__device__ __forceinline__ void mma16832f8(float* c, const uint32_t* a,
                                           uint32_t b0, uint32_t b1) {
    asm volatile(
        "mma.sync.aligned.m16n8k32.row.col.f32.e4m3.e4m3.f32 "
        "{%0,%1,%2,%3}, {%4,%5,%6,%7}, {%8,%9}, {%0,%1,%2,%3};"
        : "+f"(c[0]), "+f"(c[1]), "+f"(c[2]), "+f"(c[3])
        : "r"(a[0]), "r"(a[1]), "r"(a[2]), "r"(a[3]), "r"(b0), "r"(b1));
}
__device__ __forceinline__ uint16_t f2_to_e4m3x2(float x0, float x1) {
    return (uint16_t)__nv_cvt_float2_to_fp8x2(make_float2(x0, x1),
                                              __NV_SATFINITE, __NV_E4M3);
}

// ---------------------------------------------------------------------------
// GroupNorm -> bf16 [c, hw]
// ---------------------------------------------------------------------------
__global__ __launch_bounds__(256) void groupnorm_kernel(
    const float* __restrict__ x, const float* __restrict__ scale,
    const float* __restrict__ bias, __nv_bfloat16* __restrict__ xn)
{
    const int b = blockIdx.x / NGRP, g = blockIdx.x % NGRP;
    const size_t base = ((size_t)b * CH + (size_t)g * CPG) * HW;
    const int n4 = CPG * HW / 4;

    const float4* xin = reinterpret_cast<const float4*>(x + base);
    float s = 0.f, ss = 0.f;
    for (int i = threadIdx.x; i < n4; i += 256) {
        float4 t = xin[i];
        s  += t.x + t.y + t.z + t.w;
        ss += t.x * t.x + t.y * t.y + t.z * t.z + t.w * t.w;
    }
    __shared__ float r1[256], r2[256];
    r1[threadIdx.x] = s; r2[threadIdx.x] = ss;
    __syncthreads();
    for (int off = 128; off > 0; off >>= 1) {
        if (threadIdx.x < off) {
            r1[threadIdx.x] += r1[threadIdx.x + off];
            r2[threadIdx.x] += r2[threadIdx.x + off];
        }
        __syncthreads();
    }
    const float inv_n = 1.f / (float)(CPG * HW);
    const float mean = r1[0] * inv_n;
    const float var  = fmaxf(r2[0] * inv_n - mean * mean, 0.f);
    const float rstd = rsqrtf(var + 1e-6f);

    uint2* xo = reinterpret_cast<uint2*>(xn + base);
    for (int i = threadIdx.x; i < n4; i += 256) {
        const int c = g * CPG + (i >> 10);
        const float a = scale[c] * rstd;
        const float d = bias[c] - mean * a;
        float4 t = xin[i];
        __nv_bfloat162 h0 = __floats2bfloat162_rn(t.x * a + d, t.y * a + d);
        __nv_bfloat162 h1 = __floats2bfloat162_rn(t.z * a + d, t.w * a + d);
        uint2 o;
        o.x = *reinterpret_cast<uint32_t*>(&h0);
        o.y = *reinterpret_cast<uint32_t*>(&h1);
        xo[i] = o;
    }
}

// ---------------------------------------------------------------------------
// bf16 transpose [R, C] -> [C, R]
// ---------------------------------------------------------------------------
__global__ __launch_bounds__(256) void transpose_bf16(
    const __nv_bfloat16* __restrict__ in, __nv_bfloat16* __restrict__ out,
    int R, int C)
{
    __shared__ uint16_t tile[64][72];
    const size_t zoff = (size_t)blockIdx.z * (size_t)R * C;
    const int r0 = blockIdx.y * 64, c0 = blockIdx.x * 64;

    #pragma unroll
    for (int it = 0; it < 2; it++) {
        int idx = threadIdx.x + it * 256;
        int r = idx >> 3, c8 = idx & 7;
        uint4 v = *reinterpret_cast<const uint4*>(in + zoff + (size_t)(r0 + r) * C + c0 + c8 * 8);
        *reinterpret_cast<uint4*>(&tile[r][c8 * 8]) = v;
    }
    __syncthreads();
    #pragma unroll
    for (int it = 0; it < 2; it++) {
        int idx = threadIdx.x + it * 256;
        int c = idx >> 3, r8 = idx & 7;
        uint16_t tmp[8];
        #pragma unroll
        for (int i = 0; i < 8; i++) tmp[i] = tile[r8 * 8 + i][c];
        *reinterpret_cast<uint4*>(out + zoff + (size_t)(c0 + c) * R + r0 + r8 * 8) =
            *reinterpret_cast<uint4*>(tmp);
    }
}

// ---------------------------------------------------------------------------
// weights fp32 -> bf16
// ---------------------------------------------------------------------------
__global__ __launch_bounds__(256) void cvt_w_kernel(
    const float* __restrict__ a, const float* __restrict__ b,
    const float* __restrict__ c, const float* __restrict__ d,
    __nv_bfloat16* __restrict__ w)
{
    const int i = blockIdx.x * 256 + threadIdx.x;
    const float* s = (blockIdx.y == 0) ? a : (blockIdx.y == 1) ? b : (blockIdx.y == 2) ? c : d;
    w[(size_t)blockIdx.y * CC + i] = __float2bfloat16(s[i]);
}

// ---------------------------------------------------------------------------
// Unified tensor-core GEMM: D[M,N] = alpha * A[M,K] @ B[N,K]^T (+biases, +addc)
// IT: 0 = bf16 inputs (mma k16), 1 = fp8 e4m3 inputs (mma k32)
// OT: 0 = fp32 out, 1 = bf16 out, 2 = fp8 out
// BM=BN=128, 64 K-elems per chunk, 3-stage cp.async, 8 warps (4Mx2N).
// ---------------------------------------------------------------------------
template<int IT, int OT>
__global__ void __launch_bounds__(256, 2) gemm_tc(
    const void* __restrict__ Ag, const void* __restrict__ Bg,
    void* __restrict__ Cout,
    const float* __restrict__ bias_m, const float* __restrict__ bias_n,
    int M, int N, int K, float alpha, float addc,
    size_t sA, size_t sB, size_t sC)
{
    constexpr int ES    = (IT == 0) ? 2 : 1;   // bytes per element
    constexpr int ROWB  = 64 * ES;             // tile row bytes (64 K-elems)
    constexpr int PITCH = ROWB + 16;
    constexpr int OPSZ  = 128 * PITCH;
    constexpr int STG   = 2 * OPSZ;
    constexpr int CPR   = ROWB / 16;           // 16B chunks per row (8 / 4)
    constexpr int NSLOT = CPR / 2;             // cp.async slots/thread (4 / 2)
    constexpr int NKF   = (IT == 0) ? 4 : 2;   // mma k-steps per chunk

    extern __shared__ __align__(16) char smem[];
    const uint32_t sb = smem_u32(smem);

    const int tid  = threadIdx.x;
    const int lane = tid & 31;
    const int wid  = tid >> 5;
    const int wm   = wid >> 1;              // 0..3
    const int wn   = wid & 1;               // 0..1
    const int bm = blockIdx.y * 128;
    const int bn = blockIdx.x * 128;

    const uint8_t* Ab = (const uint8_t*)Ag + ((size_t)blockIdx.z * sA + (size_t)bm * K) * ES;
    const uint8_t* Bb = (const uint8_t*)Bg + ((size_t)blockIdx.z * sB + (size_t)bn * K) * ES;

    int rr[NSLOT];
    uint32_t so[NSLOT], go[NSLOT];
    #pragma unroll
    for (int j = 0; j < NSLOT; j++) {
        const int idx = tid + j * 256;
        rr[j] = idx / CPR;
        const int cc = idx % CPR;
        so[j] = (uint32_t)rr[j] * PITCH + cc * 16;
        go[j] = cc * 16;                         // byte offset within row chunk
    }

    const int nk = K >> 6;

    // prologue: stages 0,1
    #pragma unroll
    for (int s = 0; s < 2; s++) {
        const uint32_t kb = (uint32_t)s * ROWB;  // byte offset for this chunk
        const uint32_t st = sb + s * STG;
        #pragma unroll
        for (int j = 0; j < NSLOT; j++) {
            cp16(st + so[j],        Ab + (size_t)rr[j] * K * ES + kb + go[j]);
            cp16(st + OPSZ + so[j], Bb + (size_t)rr[j] * K * ES + kb + go[j]);
        }
        CP_COMMIT();
    }

    float acc[2][8][4];
    #pragma unroll
    for (int i = 0; i < 2; i++)
        #pragma unroll
        for (int j = 0; j < 8; j++)
            #pragma unroll
            for (int t = 0; t < 4; t++) acc[i][j][t] = 0.f;

    const uint32_t lrow = lane & 15;
    const uint32_t lsel = (lane >> 4) * 16;

    int buf = 0;
    for (int ck = 0; ck < nk; ck++) {
        CP_WAIT1();
        __syncthreads();

        if (ck + 2 < nk) {
            const uint32_t kb = (uint32_t)(ck + 2) * ROWB;
            const uint32_t st = sb + ((buf + 2) % 3) * STG;
            #pragma unroll
            for (int j = 0; j < NSLOT; j++) {
                cp16(st + so[j],        Ab + (size_t)rr[j] * K * ES + kb + go[j]);
                cp16(st + OPSZ + so[j], Bb + (size_t)rr[j] * K * ES + kb + go[j]);
            }
        }
        CP_COMMIT();

        const uint32_t sa  = sb + buf * STG;
        const uint32_t sbm = sa + OPSZ;
        #pragma unroll
        for (int kf = 0; kf < NKF; kf++) {
            const uint32_t kofs = kf * 32 + lsel;
            uint32_t ar[2][4];
            #pragma unroll
            for (int mi = 0; mi < 2; mi++)
                ldsm_x4(ar[mi], sa + (wm * 32 + mi * 16 + lrow) * PITCH + kofs);
            uint32_t br[4][4];
            #pragma unroll
            for (int nb = 0; nb < 4; nb++)
                ldsm_x4(br[nb], sbm + (wn * 64 + nb * 16 + lrow) * PITCH + kofs);
            #pragma unroll
            for (int mi = 0; mi < 2; mi++)
                #pragma unroll
                for (int nj = 0; nj < 8; nj++) {
                    const int nb = nj >> 1, od = nj & 1;
                    if (IT == 0)
                        mma16816(acc[mi][nj], ar[mi], br[nb][od], br[nb][od + 2]);
                    else
                        mma16832f8(acc[mi][nj], ar[mi], br[nb][od], br[nb][od + 2]);
                }
        }
        buf = (buf + 1) % 3;
        // no trailing barrier: writes at iter ck target buffer (ck+2)%3,
        // whose readers finished before this iteration's leading barrier.
    }

    // ---- epilogue ----
    const int gid = lane >> 2, tig = lane & 3;
    #pragma unroll
    for (int mi = 0; mi < 2; mi++) {
        #pragma unroll
        for (int r2 = 0; r2 < 2; r2++) {
            const int m = bm + wm * 32 + mi * 16 + gid + r2 * 8;
            const float bmv = (bias_m ? bias_m[m] : 0.f) + addc;
            #pragma unroll
            for (int nj = 0; nj < 8; nj++) {
                const int n = bn + wn * 64 + nj * 8 + tig * 2;
                float x0 = acc[mi][nj][r2 * 2]     * alpha + bmv;
                float x1 = acc[mi][nj][r2 * 2 + 1] * alpha + bmv;
                if (bias_n) { x0 += bias_n[n]; x1 += bias_n[n + 1]; }
                const size_t off = (size_t)blockIdx.z * sC + (size_t)m * N + n;
                if (OT == 1) {
                    __nv_bfloat162 h = __floats2bfloat162_rn(x0, x1);
                    *reinterpret_cast<uint32_t*>((__nv_bfloat16*)Cout + off)
                        = *reinterpret_cast<uint32_t*>(&h);
                } else if (OT == 0) {
                    *reinterpret_cast<float2*>((float*)Cout + off) = make_float2(x0, x1);
                } else {
                    *reinterpret_cast<uint16_t*>((uint8_t*)Cout + off)
                        = f2_to_e4m3x2(x0, x1);
                }
            }
        }
    }
}

// ---------------------------------------------------------------------------
// Row softmax: bf16 in -> fp8 out scaled by 256. One block per 4096-row.
// ---------------------------------------------------------------------------
__global__ __launch_bounds__(256) void softmax_kernel(
    const __nv_bfloat16* __restrict__ s, uint8_t* __restrict__ at)
{
    const uint4* r4 = reinterpret_cast<const uint4*>(s + (size_t)blockIdx.x * HW);
    uint4* o4 = reinterpret_cast<uint4*>(at + (size_t)blockIdx.x * HW);

    float v[16];
    #pragma unroll
    for (int i = 0; i < 2; i++) {
        uint4 t = r4[threadIdx.x * 2 + i];        // 16 contiguous bf16 / thread
        const uint32_t* u = reinterpret_cast<const uint32_t*>(&t);
        #pragma unroll
        for (int j = 0; j < 4; j++) {
            float2 f = __bfloat1622float2(*reinterpret_cast<const __nv_bfloat162*>(&u[j]));
            v[i * 8 + j * 2]     = f.x;
            v[i * 8 + j * 2 + 1] = f.y;
        }
    }
    float mx = -1e30f;
    #pragma unroll
    for (int i = 0; i < 16; i++) mx = fmaxf(mx, v[i]);

    __shared__ float red[256];
    red[threadIdx.x] = mx;
    __syncthreads();
    for (int off = 128; off > 0; off >>= 1) {
        if (threadIdx.x < off)
            red[threadIdx.x] = fmaxf(red[threadIdx.x], red[threadIdx.x + off]);
        __syncthreads();
    }
    mx = red[0];
    __syncthreads();

    float sum = 0.f;
    #pragma unroll
    for (int i = 0; i < 16; i++) { v[i] = __expf(v[i] - mx); sum += v[i]; }
    red[threadIdx.x] = sum;
    __syncthreads();
    for (int off = 128; off > 0; off >>= 1) {
        if (threadIdx.x < off) red[threadIdx.x] += red[threadIdx.x + off];
        __syncthreads();
    }
    const float inv = 256.f / red[0];   // x256 scale folded in (fp8 range)

    uint4 t;
    uint32_t* u = reinterpret_cast<uint32_t*>(&t);
    #pragma unroll
    for (int j = 0; j < 4; j++) {
        uint32_t lo = f2_to_e4m3x2(v[j * 4 + 0] * inv, v[j * 4 + 1] * inv);
        uint32_t hi = f2_to_e4m3x2(v[j * 4 + 2] * inv, v[j * 4 + 3] * inv);
        u[j] = lo | (hi << 16);
    }
    o4[threadIdx.x] = t;
}

// ---------------------------------------------------------------------------
// Launch
// ---------------------------------------------------------------------------
#define SMEM_B16 110592    // 3 * 2 * 128 * 144
#define SMEM_F8  61440     // 3 * 2 * 128 * 80

extern "C" void kernel_launch(void* const* d_in, const int* in_sizes, int n_in,
                              void* d_out, int out_size)
{
    const float* x  = (const float*)d_in[0];
    const float* gs = (const float*)d_in[1];
    const float* gb = (const float*)d_in[2];
    const float* wq = (const float*)d_in[3];
    const float* bq = (const float*)d_in[4];
    const float* wk = (const float*)d_in[5];
    const float* bk = (const float*)d_in[6];
    const float* wv = (const float*)d_in[7];
    const float* bv = (const float*)d_in[8];
    const float* wp = (const float*)d_in[9];
    const float* bp = (const float*)d_in[10];
    float* out = (float*)d_out;

    __nv_bfloat16 *xn, *xnT, *s, *o2, *w;
    uint8_t *q, *k, *v, *at;
    cudaGetSymbolAddress((void**)&xn,  g_xn);
    cudaGetSymbolAddress((void**)&xnT, g_xnT);
    cudaGetSymbolAddress((void**)&q,   g_q);
    cudaGetSymbolAddress((void**)&k,   g_k);
    cudaGetSymbolAddress((void**)&v,   g_v);
    cudaGetSymbolAddress((void**)&s,   g_s);
    cudaGetSymbolAddress((void**)&at,  g_at);
    cudaGetSymbolAddress((void**)&o2,  g_o2);
    cudaGetSymbolAddress((void**)&w,   g_w);

    cudaFuncSetAttribute(gemm_tc<0, 2>, cudaFuncAttributeMaxDynamicSharedMemorySize, SMEM_B16);
    cudaFuncSetAttribute(gemm_tc<0, 0>, cudaFuncAttributeMaxDynamicSharedMemorySize, SMEM_B16);
    cudaFuncSetAttribute(gemm_tc<1, 1>, cudaFuncAttributeMaxDynamicSharedMemorySize, SMEM_F8);

    // 0) weights -> bf16
    cvt_w_kernel<<<dim3(CC / 256, 4), 256>>>(wq, wk, wv, wp, w);

    // 1) GroupNorm
    groupnorm_kernel<<<BATCH * NGRP, 256>>>(x, gs, gb, xn);

    // 2) transpose xn -> xnT [hw, c]
    transpose_bf16<<<dim3(HW / 64, CH / 64, BATCH), 256>>>(xn, xnT, CH, HW);

    // 3) Q, K -> fp8 [hw, c]: D = xnT @ W^T + b  (bias over N)
    dim3 gQK(CH / 128, HW / 128, BATCH);
    gemm_tc<0, 2><<<gQK, 256, SMEM_B16>>>(xnT, w,      q, nullptr, bq, HW, CH, CH, 1.f, 0.f, CHW, 0, CHW);
    gemm_tc<0, 2><<<gQK, 256, SMEM_B16>>>(xnT, w + CC, k, nullptr, bk, HW, CH, CH, 1.f, 0.f, CHW, 0, CHW);

    // 4) V -> fp8 [c, hw]: D = Wv @ xnT^T + b  (bias over M)
    dim3 gV(HW / 128, CH / 128, BATCH);
    gemm_tc<0, 2><<<gV, 256, SMEM_B16>>>(w + 2 * CC, xnT, v, bv, nullptr, CH, HW, CH, 1.f, 0.f, 0, CHW, CHW);

    // 5) scores bf16 (fp8 inputs)
    const float alpha = 1.0f / sqrtf((float)CH);
    dim3 gS(HW / 128, HW / 128, BATCH);
    gemm_tc<1, 1><<<gS, 256, SMEM_F8>>>(q, k, s, nullptr, nullptr, HW, HW, CH, alpha, 0.f, CHW, CHW, SHW);

    // 6) softmax -> fp8 attn*256
    softmax_kernel<<<BATCH * HW, 256>>>(s, at);

    // 7) o2[hw, c] = attn @ v^T (fp8 inputs), alpha undoes the 256 scale
    dim3 gO(CH / 128, HW / 128, BATCH);
    gemm_tc<1, 1><<<gO, 256, SMEM_F8>>>(at, v, o2, nullptr, nullptr, HW, CH, HW, 1.f / 256.f, 0.f, SHW, CHW, CHW);

    // 8) proj fp32 + bias + 64: out[co, i] = Wp @ o2^T
    gemm_tc<0, 0><<<gV, 256, SMEM_B16>>>(w + 3 * CC, o2, out, bp, nullptr, CH, HW, CH, 1.f, 64.0f, 0, CHW, CHW);
}

// round 6
// speedup vs baseline: 6.7025x; 1.0390x over previous
#include <cuda_runtime.h>
#include <cuda_bf16.h>
#include <cuda_fp16.h>
#include <cuda_fp8.h>
#include <cstdint>
#include <math.h>

#define BATCH 4
#define CH    512
#define HW    4096
#define NGRP  32
#define CPG   16

static const size_t CHW = (size_t)CH * HW;
static const size_t SHW = (size_t)HW * HW;
#define CC (CH * CH)

// ---------------- scratch ----------------
__device__ __nv_bfloat16 g_xn [BATCH * CH * HW];   // [c, hw] bf16
__device__ __nv_bfloat16 g_xnT[BATCH * CH * HW];   // [hw, c] bf16
__device__ uint8_t       g_q  [BATCH * CH * HW];   // [hw, c] fp8
__device__ uint8_t       g_k  [BATCH * CH * HW];   // [hw, c] fp8
__device__ uint8_t       g_v  [BATCH * CH * HW];   // [c, hw] fp8
__device__ __nv_bfloat16 g_s  [BATCH * HW * HW];   // bf16 scores (128 MB)
__device__ uint8_t       g_at [BATCH * HW * HW];   // fp8 attn*256 (64 MB)
__device__ __nv_bfloat16 g_o2 [BATCH * CH * HW];   // [hw, c] bf16
__device__ __nv_bfloat16 g_w  [4 * CH * CH];       // wq, wk, wv, wp bf16

// ---------------- PTX helpers (family-portable) ----------------
__device__ __forceinline__ uint32_t smem_u32(const void* p) {
    uint32_t a;
    asm("{ .reg .u64 t; cvta.to.shared.u64 t, %1; cvt.u32.u64 %0, t; }"
        : "=r"(a) : "l"(p));
    return a;
}
__device__ __forceinline__ void cp16(uint32_t s, const void* g) {
    asm volatile("cp.async.cg.shared.global [%0], [%1], 16;"
                 :: "r"(s), "l"(__cvta_generic_to_global(g)) : "memory");
}
#define CP_COMMIT() asm volatile("cp.async.commit_group;" ::: "memory")
#define CP_WAIT1()  asm volatile("cp.async.wait_group 1;"  ::: "memory")

__device__ __forceinline__ void ldsm_x4(uint32_t* r, uint32_t addr) {
    asm volatile("ldmatrix.sync.aligned.m8n8.x4.shared.b16 {%0,%1,%2,%3}, [%4];"
        : "=r"(r[0]), "=r"(r[1]), "=r"(r[2]), "=r"(r[3]) : "r"(addr));
}
__device__ __forceinline__ void mma16816(float* c, const uint32_t* a,
                                         uint32_t b0, uint32_t b1) {
    asm volatile(
        "mma.sync.aligned.m16n8k16.row.col.f32.bf16.bf16.f32 "
        "{%0,%1,%2,%3}, {%4,%5,%6,%7}, {%8,%9}, {%0,%1,%2,%3};"
        : "+f"(c[0]), "+f"(c[1]), "+f"(c[2]), "+f"(c[3])
        : "r"(a[0]), "r"(a[1]), "r"(a[2]), "r"(a[3]), "r"(b0), "r"(b1));
}
// fp8 e4m3 inputs, f16 accumulator (2 packed regs)
__device__ __forceinline__ void mma_f8h(uint32_t* c, const uint32_t* a,
                                        uint32_t b0, uint32_t b1) {
    asm volatile(
        "mma.sync.aligned.m16n8k32.row.col.f16.e4m3.e4m3.f16 "
        "{%0,%1}, {%2,%3,%4,%5}, {%6,%7}, {%0,%1};"
        : "+r"(c[0]), "+r"(c[1])
        : "r"(a[0]), "r"(a[1]), "r"(a[2]), "r"(a[3]), "r"(b0), "r"(b1));
}
__device__ __forceinline__ uint16_t f2_to_e4m3x2(float x0, float x1) {
    return (uint16_t)__nv_cvt_float2_to_fp8x2(make_float2(x0, x1),
                                              __NV_SATFINITE, __NV_E4M3);
}

// ---------------------------------------------------------------------------
// GroupNorm -> bf16 [c, hw]
// ---------------------------------------------------------------------------
__global__ __launch_bounds__(256) void groupnorm_kernel(
    const float* __restrict__ x, const float* __restrict__ scale,
    const float* __restrict__ bias, __nv_bfloat16* __restrict__ xn)
{
    const int b = blockIdx.x / NGRP, g = blockIdx.x % NGRP;
    const size_t base = ((size_t)b * CH + (size_t)g * CPG) * HW;
    const int n4 = CPG * HW / 4;

    const float4* xin = reinterpret_cast<const float4*>(x + base);
    float s = 0.f, ss = 0.f;
    for (int i = threadIdx.x; i < n4; i += 256) {
        float4 t = xin[i];
        s  += t.x + t.y + t.z + t.w;
        ss += t.x * t.x + t.y * t.y + t.z * t.z + t.w * t.w;
    }
    __shared__ float r1[256], r2[256];
    r1[threadIdx.x] = s; r2[threadIdx.x] = ss;
    __syncthreads();
    for (int off = 128; off > 0; off >>= 1) {
        if (threadIdx.x < off) {
            r1[threadIdx.x] += r1[threadIdx.x + off];
            r2[threadIdx.x] += r2[threadIdx.x + off];
        }
        __syncthreads();
    }
    const float inv_n = 1.f / (float)(CPG * HW);
    const float mean = r1[0] * inv_n;
    const float var  = fmaxf(r2[0] * inv_n - mean * mean, 0.f);
    const float rstd = rsqrtf(var + 1e-6f);

    uint2* xo = reinterpret_cast<uint2*>(xn + base);
    for (int i = threadIdx.x; i < n4; i += 256) {
        const int c = g * CPG + (i >> 10);
        const float a = scale[c] * rstd;
        const float d = bias[c] - mean * a;
        float4 t = xin[i];
        __nv_bfloat162 h0 = __floats2bfloat162_rn(t.x * a + d, t.y * a + d);
        __nv_bfloat162 h1 = __floats2bfloat162_rn(t.z * a + d, t.w * a + d);
        uint2 o;
        o.x = *reinterpret_cast<uint32_t*>(&h0);
        o.y = *reinterpret_cast<uint32_t*>(&h1);
        xo[i] = o;
    }
}

// ---------------------------------------------------------------------------
// bf16 transpose [R, C] -> [C, R]
// ---------------------------------------------------------------------------
__global__ __launch_bounds__(256) void transpose_bf16(
    const __nv_bfloat16* __restrict__ in, __nv_bfloat16* __restrict__ out,
    int R, int C)
{
    __shared__ uint16_t tile[64][72];
    const size_t zoff = (size_t)blockIdx.z * (size_t)R * C;
    const int r0 = blockIdx.y * 64, c0 = blockIdx.x * 64;

    #pragma unroll
    for (int it = 0; it < 2; it++) {
        int idx = threadIdx.x + it * 256;
        int r = idx >> 3, c8 = idx & 7;
        uint4 v = *reinterpret_cast<const uint4*>(in + zoff + (size_t)(r0 + r) * C + c0 + c8 * 8);
        *reinterpret_cast<uint4*>(&tile[r][c8 * 8]) = v;
    }
    __syncthreads();
    #pragma unroll
    for (int it = 0; it < 2; it++) {
        int idx = threadIdx.x + it * 256;
        int c = idx >> 3, r8 = idx & 7;
        uint16_t tmp[8];
        #pragma unroll
        for (int i = 0; i < 8; i++) tmp[i] = tile[r8 * 8 + i][c];
        *reinterpret_cast<uint4*>(out + zoff + (size_t)(c0 + c) * R + r0 + r8 * 8) =
            *reinterpret_cast<uint4*>(tmp);
    }
}

// ---------------------------------------------------------------------------
// weights fp32 -> bf16
// ---------------------------------------------------------------------------
__global__ __launch_bounds__(256) void cvt_w_kernel(
    const float* __restrict__ a, const float* __restrict__ b,
    const float* __restrict__ c, const float* __restrict__ d,
    __nv_bfloat16* __restrict__ w)
{
    const int i = blockIdx.x * 256 + threadIdx.x;
    const float* s = (blockIdx.y == 0) ? a : (blockIdx.y == 1) ? b : (blockIdx.y == 2) ? c : d;
    w[(size_t)blockIdx.y * CC + i] = __float2bfloat16(s[i]);
}

// ---------------------------------------------------------------------------
// bf16 GEMM (QKV + proj): D[M,N] = alpha*A@B^T + bias_m + bias_n + addc
// OT: 0 = fp32 out, 2 = fp8 out. 128x128 tile, 8 warps 4Mx2N, 3 stages.
// ---------------------------------------------------------------------------
#define PITCH  144
#define OPSZ   18432           // 128 * 144
#define STG_SZ 36864
#define SMEM_B16 110592        // 3 * STG_SZ

template<int OT>
__global__ void __launch_bounds__(256, 2) gemm_tc(
    const void* __restrict__ Ag, const void* __restrict__ Bg,
    void* __restrict__ Cout,
    const float* __restrict__ bias_m, const float* __restrict__ bias_n,
    int M, int N, int K, float alpha, float addc,
    size_t sA, size_t sB, size_t sC)
{
    extern __shared__ __align__(16) char smem[];
    const uint32_t sb = smem_u32(smem);

    const int tid  = threadIdx.x;
    const int lane = tid & 31;
    const int wid  = tid >> 5;
    const int wm   = wid >> 1;
    const int wn   = wid & 1;
    const int bm = blockIdx.y * 128;
    const int bn = blockIdx.x * 128;

    const uint8_t* Ab = (const uint8_t*)Ag + ((size_t)blockIdx.z * sA + (size_t)bm * K) * 2;
    const uint8_t* Bb = (const uint8_t*)Bg + ((size_t)blockIdx.z * sB + (size_t)bn * K) * 2;

    int rr[4];
    uint32_t so[4], go[4];
    #pragma unroll
    for (int j = 0; j < 4; j++) {
        const int idx = tid + j * 256;
        rr[j] = idx >> 3;
        const int cc = idx & 7;
        so[j] = (uint32_t)rr[j] * PITCH + cc * 16;
        go[j] = cc * 16;
    }

    const int nk = K >> 6;   // 64 bf16 = 128 B per chunk

    #pragma unroll
    for (int s = 0; s < 2; s++) {
        const uint32_t kb = (uint32_t)s * 128;
        const uint32_t st = sb + s * STG_SZ;
        #pragma unroll
        for (int j = 0; j < 4; j++) {
            cp16(st + so[j],        Ab + (size_t)rr[j] * K * 2 + kb + go[j]);
            cp16(st + OPSZ + so[j], Bb + (size_t)rr[j] * K * 2 + kb + go[j]);
        }
        CP_COMMIT();
    }

    float acc[2][8][4];
    #pragma unroll
    for (int i = 0; i < 2; i++)
        #pragma unroll
        for (int j = 0; j < 8; j++)
            #pragma unroll
            for (int t = 0; t < 4; t++) acc[i][j][t] = 0.f;

    const uint32_t lrow = lane & 15;
    const uint32_t lsel = (lane >> 4) * 16;

    int buf = 0;
    for (int ck = 0; ck < nk; ck++) {
        CP_WAIT1();
        __syncthreads();

        if (ck + 2 < nk) {
            const uint32_t kb = (uint32_t)(ck + 2) * 128;
            const uint32_t st = sb + ((buf + 2) % 3) * STG_SZ;
            #pragma unroll
            for (int j = 0; j < 4; j++) {
                cp16(st + so[j],        Ab + (size_t)rr[j] * K * 2 + kb + go[j]);
                cp16(st + OPSZ + so[j], Bb + (size_t)rr[j] * K * 2 + kb + go[j]);
            }
        }
        CP_COMMIT();

        const uint32_t sa  = sb + buf * STG_SZ;
        const uint32_t sbm = sa + OPSZ;
        #pragma unroll
        for (int kf = 0; kf < 4; kf++) {
            const uint32_t kofs = kf * 32 + lsel;
            uint32_t ar[2][4];
            #pragma unroll
            for (int mi = 0; mi < 2; mi++)
                ldsm_x4(ar[mi], sa + (wm * 32 + mi * 16 + lrow) * PITCH + kofs);
            uint32_t br[4][4];
            #pragma unroll
            for (int nb = 0; nb < 4; nb++)
                ldsm_x4(br[nb], sbm + (wn * 64 + nb * 16 + lrow) * PITCH + kofs);
            #pragma unroll
            for (int mi = 0; mi < 2; mi++)
                #pragma unroll
                for (int nj = 0; nj < 8; nj++) {
                    const int nb = nj >> 1, od = nj & 1;
                    mma16816(acc[mi][nj], ar[mi], br[nb][od], br[nb][od + 2]);
                }
        }
        buf = (buf + 1) % 3;
    }

    const int gid = lane >> 2, tig = lane & 3;
    #pragma unroll
    for (int mi = 0; mi < 2; mi++) {
        #pragma unroll
        for (int r2 = 0; r2 < 2; r2++) {
            const int m = bm + wm * 32 + mi * 16 + gid + r2 * 8;
            const float bmv = (bias_m ? bias_m[m] : 0.f) + addc;
            #pragma unroll
            for (int nj = 0; nj < 8; nj++) {
                const int n = bn + wn * 64 + nj * 8 + tig * 2;
                float x0 = acc[mi][nj][r2 * 2]     * alpha + bmv;
                float x1 = acc[mi][nj][r2 * 2 + 1] * alpha + bmv;
                if (bias_n) { x0 += bias_n[n]; x1 += bias_n[n + 1]; }
                const size_t off = (size_t)blockIdx.z * sC + (size_t)m * N + n;
                if (OT == 0) {
                    *reinterpret_cast<float2*>((float*)Cout + off) = make_float2(x0, x1);
                } else {
                    *reinterpret_cast<uint16_t*>((uint8_t*)Cout + off)
                        = f2_to_e4m3x2(x0, x1);
                }
            }
        }
    }
}

// ---------------------------------------------------------------------------
// fp8 attention GEMM, f16 accumulate: D[M,N] = alpha * A[M,K] @ B[N,K]^T
// 128x128 tile, 4 warps (2x2 grid of 64x64 warp tiles), 128 threads.
// K-chunk = 128 fp8 elems (128 B rows), 3-stage cp.async. bf16 output.
// ---------------------------------------------------------------------------
__global__ void __launch_bounds__(128, 2) gemm_f8h(
    const uint8_t* __restrict__ A, const uint8_t* __restrict__ B,
    __nv_bfloat16* __restrict__ C,
    int M, int N, int K, float alpha,
    size_t sA, size_t sB, size_t sC)
{
    extern __shared__ __align__(16) char smem[];
    const uint32_t sb = smem_u32(smem);

    const int tid  = threadIdx.x;
    const int lane = tid & 31;
    const int wid  = tid >> 5;
    const int wm   = wid >> 1;       // 0..1
    const int wn   = wid & 1;        // 0..1
    const int bm = blockIdx.y * 128;
    const int bn = blockIdx.x * 128;

    const uint8_t* Ab = A + (size_t)blockIdx.z * sA + (size_t)bm * K;
    const uint8_t* Bb = B + (size_t)blockIdx.z * sB + (size_t)bn * K;

    // cp.async: 8 slots/thread/operand (128 rows x 8 x 16B chunks / 128 thr)
    uint32_t so[8], gA[8];
    #pragma unroll
    for (int j = 0; j < 8; j++) {
        const int idx = tid + j * 128;
        const int row = idx >> 3, cc = idx & 7;
        so[j] = (uint32_t)row * PITCH + cc * 16;
        gA[j] = (uint32_t)row * K + cc * 16;     // global byte offset (<16 MB)
    }

    const int nk = K >> 7;   // 128 fp8 per chunk

    #pragma unroll
    for (int s = 0; s < 2; s++) {
        const uint32_t kb = (uint32_t)s * 128;
        const uint32_t st = sb + s * STG_SZ;
        #pragma unroll
        for (int j = 0; j < 8; j++) {
            cp16(st + so[j],        Ab + gA[j] + kb);
            cp16(st + OPSZ + so[j], Bb + gA[j] + kb);
        }
        CP_COMMIT();
    }

    uint32_t acc[4][8][2];
    #pragma unroll
    for (int i = 0; i < 4; i++)
        #pragma unroll
        for (int j = 0; j < 8; j++) { acc[i][j][0] = 0u; acc[i][j][1] = 0u; }

    const uint32_t lrow = lane & 15;
    const uint32_t lsel = (lane >> 4) * 16;

    int buf = 0;
    for (int ck = 0; ck < nk; ck++) {
        CP_WAIT1();
        __syncthreads();

        if (ck + 2 < nk) {
            const uint32_t kb = (uint32_t)(ck + 2) * 128;
            const uint32_t st = sb + ((buf + 2) % 3) * STG_SZ;
            #pragma unroll
            for (int j = 0; j < 8; j++) {
                cp16(st + so[j],        Ab + gA[j] + kb);
                cp16(st + OPSZ + so[j], Bb + gA[j] + kb);
            }
        }
        CP_COMMIT();

        const uint32_t sa  = sb + buf * STG_SZ;
        const uint32_t sbm = sa + OPSZ;
        #pragma unroll
        for (int kf = 0; kf < 4; kf++) {
            const uint32_t kofs = kf * 32 + lsel;
            uint32_t ar[4][4];
            #pragma unroll
            for (int mi = 0; mi < 4; mi++)
                ldsm_x4(ar[mi], sa + (wm * 64 + mi * 16 + lrow) * PITCH + kofs);
            uint32_t br[4][4];
            #pragma unroll
            for (int nb = 0; nb < 4; nb++)
                ldsm_x4(br[nb], sbm + (wn * 64 + nb * 16 + lrow) * PITCH + kofs);
            #pragma unroll
            for (int mi = 0; mi < 4; mi++)
                #pragma unroll
                for (int nj = 0; nj < 8; nj++) {
                    const int nb = nj >> 1, od = nj & 1;
                    mma_f8h(acc[mi][nj], ar[mi], br[nb][od], br[nb][od + 2]);
                }
        }
        buf = (buf + 1) % 3;
    }

    // ---- epilogue: unpack f16 pairs, scale, store bf16 ----
    const int gid = lane >> 2, tig = lane & 3;
    #pragma unroll
    for (int mi = 0; mi < 4; mi++) {
        #pragma unroll
        for (int r2 = 0; r2 < 2; r2++) {
            const int m = bm + wm * 64 + mi * 16 + gid + r2 * 8;
            #pragma unroll
            for (int nj = 0; nj < 8; nj++) {
                const int n = bn + wn * 64 + nj * 8 + tig * 2;
                const __half2 h = *reinterpret_cast<const __half2*>(&acc[mi][nj][r2]);
                const float2 f = __half22float2(h);
                __nv_bfloat162 ob = __floats2bfloat162_rn(f.x * alpha, f.y * alpha);
                *reinterpret_cast<uint32_t*>(C + (size_t)blockIdx.z * sC + (size_t)m * N + n)
                    = *reinterpret_cast<uint32_t*>(&ob);
            }
        }
    }
}

// ---------------------------------------------------------------------------
// Row softmax: bf16 in -> fp8 out scaled by 256. One block per 4096-row.
// ---------------------------------------------------------------------------
__global__ __launch_bounds__(256) void softmax_kernel(
    const __nv_bfloat16* __restrict__ s, uint8_t* __restrict__ at)
{
    const uint4* r4 = reinterpret_cast<const uint4*>(s + (size_t)blockIdx.x * HW);
    uint4* o4 = reinterpret_cast<uint4*>(at + (size_t)blockIdx.x * HW);

    float v[16];
    #pragma unroll
    for (int i = 0; i < 2; i++) {
        uint4 t = r4[threadIdx.x * 2 + i];
        const uint32_t* u = reinterpret_cast<const uint32_t*>(&t);
        #pragma unroll
        for (int j = 0; j < 4; j++) {
            float2 f = __bfloat1622float2(*reinterpret_cast<const __nv_bfloat162*>(&u[j]));
            v[i * 8 + j * 2]     = f.x;
            v[i * 8 + j * 2 + 1] = f.y;
        }
    }
    float mx = -1e30f;
    #pragma unroll
    for (int i = 0; i < 16; i++) mx = fmaxf(mx, v[i]);

    __shared__ float red[256];
    red[threadIdx.x] = mx;
    __syncthreads();
    for (int off = 128; off > 0; off >>= 1) {
        if (threadIdx.x < off)
            red[threadIdx.x] = fmaxf(red[threadIdx.x], red[threadIdx.x + off]);
        __syncthreads();
    }
    mx = red[0];
    __syncthreads();

    float sum = 0.f;
    #pragma unroll
    for (int i = 0; i < 16; i++) { v[i] = __expf(v[i] - mx); sum += v[i]; }
    red[threadIdx.x] = sum;
    __syncthreads();
    for (int off = 128; off > 0; off >>= 1) {
        if (threadIdx.x < off) red[threadIdx.x] += red[threadIdx.x + off];
        __syncthreads();
    }
    const float inv = 256.f / red[0];

    uint4 t;
    uint32_t* u = reinterpret_cast<uint32_t*>(&t);
    #pragma unroll
    for (int j = 0; j < 4; j++) {
        uint32_t lo = f2_to_e4m3x2(v[j * 4 + 0] * inv, v[j * 4 + 1] * inv);
        uint32_t hi = f2_to_e4m3x2(v[j * 4 + 2] * inv, v[j * 4 + 3] * inv);
        u[j] = lo | (hi << 16);
    }
    o4[threadIdx.x] = t;
}

// ---------------------------------------------------------------------------
// Launch
// ---------------------------------------------------------------------------
extern "C" void kernel_launch(void* const* d_in, const int* in_sizes, int n_in,
                              void* d_out, int out_size)
{
    const float* x  = (const float*)d_in[0];
    const float* gs = (const float*)d_in[1];
    const float* gb = (const float*)d_in[2];
    const float* wq = (const float*)d_in[3];
    const float* bq = (const float*)d_in[4];
    const float* wk = (const float*)d_in[5];
    const float* bk = (const float*)d_in[6];
    const float* wv = (const float*)d_in[7];
    const float* bv = (const float*)d_in[8];
    const float* wp = (const float*)d_in[9];
    const float* bp = (const float*)d_in[10];
    float* out = (float*)d_out;

    __nv_bfloat16 *xn, *xnT, *s, *o2, *w;
    uint8_t *q, *k, *v, *at;
    cudaGetSymbolAddress((void**)&xn,  g_xn);
    cudaGetSymbolAddress((void**)&xnT, g_xnT);
    cudaGetSymbolAddress((void**)&q,   g_q);
    cudaGetSymbolAddress((void**)&k,   g_k);
    cudaGetSymbolAddress((void**)&v,   g_v);
    cudaGetSymbolAddress((void**)&s,   g_s);
    cudaGetSymbolAddress((void**)&at,  g_at);
    cudaGetSymbolAddress((void**)&o2,  g_o2);
    cudaGetSymbolAddress((void**)&w,   g_w);

    cudaFuncSetAttribute(gemm_tc<2>, cudaFuncAttributeMaxDynamicSharedMemorySize, SMEM_B16);
    cudaFuncSetAttribute(gemm_tc<0>, cudaFuncAttributeMaxDynamicSharedMemorySize, SMEM_B16);
    cudaFuncSetAttribute(gemm_f8h,   cudaFuncAttributeMaxDynamicSharedMemorySize, SMEM_B16);

    // 0) weights -> bf16
    cvt_w_kernel<<<dim3(CC / 256, 4), 256>>>(wq, wk, wv, wp, w);

    // 1) GroupNorm
    groupnorm_kernel<<<BATCH * NGRP, 256>>>(x, gs, gb, xn);

    // 2) transpose xn -> xnT [hw, c]
    transpose_bf16<<<dim3(HW / 64, CH / 64, BATCH), 256>>>(xn, xnT, CH, HW);

    // 3) Q, K -> fp8 [hw, c]
    dim3 gQK(CH / 128, HW / 128, BATCH);
    gemm_tc<2><<<gQK, 256, SMEM_B16>>>(xnT, w,      q, nullptr, bq, HW, CH, CH, 1.f, 0.f, CHW, 0, CHW);
    gemm_tc<2><<<gQK, 256, SMEM_B16>>>(xnT, w + CC, k, nullptr, bk, HW, CH, CH, 1.f, 0.f, CHW, 0, CHW);

    // 4) V -> fp8 [c, hw]
    dim3 gV(HW / 128, CH / 128, BATCH);
    gemm_tc<2><<<gV, 256, SMEM_B16>>>(w + 2 * CC, xnT, v, bv, nullptr, CH, HW, CH, 1.f, 0.f, 0, CHW, CHW);

    // 5) scores bf16 (fp8 in, f16 acc)
    const float alpha = 1.0f / sqrtf((float)CH);
    dim3 gS(HW / 128, HW / 128, BATCH);
    gemm_f8h<<<gS, 128, SMEM_B16>>>(q, k, s, HW, HW, CH, alpha, CHW, CHW, SHW);

    // 6) softmax -> fp8 attn*256
    softmax_kernel<<<BATCH * HW, 256>>>(s, at);

    // 7) o2[hw, c] = attn @ v^T (fp8 in, f16 acc), alpha undoes the 256 scale
    dim3 gO(CH / 128, HW / 128, BATCH);
    gemm_f8h<<<gO, 128, SMEM_B16>>>(at, v, o2, HW, CH, HW, 1.f / 256.f, SHW, CHW, CHW);

    // 8) proj fp32 + bias + 64
    gemm_tc<0><<<gV, 256, SMEM_B16>>>(w + 3 * CC, o2, out, bp, nullptr, CH, HW, CH, 1.f, 64.0f, 0, CHW, CHW);
}